// round 1
// baseline (speedup 1.0000x reference)
#include <cuda_runtime.h>
#include <math.h>

// Problem constants
#define BB 2048
#define NN 100      // nodes
#define GG 100      // group
#define EE 128      // embedding
#define HH 8        // heads
#define DD 16       // key dim
#define NT 512      // threads per CTA

// Shared memory layout (floats). Row stride 132 (16B-aligned, odd/32 bank skew).
#define SA_OFF   0        // [100][132] enc -> last -> attn_out
#define SK_OFF   13200    // [100][132] k   -> encT [128][100]
#define SV_OFF   26400    // [100][132] v   -> S scores [100][104]
#define SQ_OFF   39600    // [100][132] q   -> mh
#define SG_OFF   52800    // [128] graph mean
#define SQG_OFF  52928    // [128] q_graph
#define SMEM_FLOATS 53056

__device__ __forceinline__ float tanh_acc(float x) {
    // tanh via exp, ~1e-6 rel error (far better than tanh.approx)
    float ax = fabsf(x);
    float e = __expf(-2.0f * ax);
    float t = __fdividef(1.0f - e, 1.0f + e);
    return copysignf(t, x);
}

__global__ __launch_bounds__(NT, 1)
void pomo_decoder_kernel(const float* __restrict__ enc,   // [B,N,E]
                         const float* __restrict__ last,  // [B,G,E]
                         const float* __restrict__ mask,  // [B,G,N]
                         const float* __restrict__ Wqg,   // [E,128]
                         const float* __restrict__ Wqf,   // [E,128]
                         const float* __restrict__ Wql,   // [E,128]
                         const float* __restrict__ Wk,    // [E,128]
                         const float* __restrict__ Wv,    // [E,128]
                         const float* __restrict__ Wc,    // [128,E]
                         const float* __restrict__ bc,    // [E]
                         float* __restrict__ out)         // [B,G,N]
{
    extern __shared__ float sm[];
    float* sA  = sm + SA_OFF;
    float* sK  = sm + SK_OFF;
    float* sV  = sm + SV_OFF;
    float* sQ  = sm + SQ_OFF;
    float* sG  = sm + SG_OFF;
    float* sQg = sm + SQG_OFF;

    const int b    = blockIdx.x;
    const int tid  = threadIdx.x;
    const int lane = tid & 31;
    const int warp = tid >> 5;   // 0..15

    const float* encB  = enc  + (size_t)b * NN * EE;
    const float* lastB = last + (size_t)b * GG * EE;
    const float* maskB = mask + (size_t)b * GG * NN;
    float*       outB  = out  + (size_t)b * GG * NN;

    // ---------------- Phase A: load enc -> sA, graph mean, q_graph -------------
    for (int idx = tid; idx < NN * 32; idx += NT) {
        int n  = idx >> 5;
        int e4 = (idx & 31) * 4;
        float4 v = *reinterpret_cast<const float4*>(encB + n * EE + e4);
        *reinterpret_cast<float4*>(sA + n * 132 + e4) = v;
    }
    __syncthreads();

    if (tid < EE) {
        float s = 0.f;
        #pragma unroll 4
        for (int n = 0; n < NN; ++n) s += sA[n * 132 + tid];
        sG[tid] = s * (1.0f / NN);
    }
    __syncthreads();

    if (tid < EE) {
        float s = 0.f;
        #pragma unroll 4
        for (int e = 0; e < EE; ++e) s += sG[e] * Wqg[e * 128 + tid];
        sQg[tid] = s;
    }
    // (no sync needed before B: B doesn't touch sQg; sync before C covers it)

    // ---------------- Phase B: k = enc@Wk, v = enc@Wv -> sK, sV ----------------
    {
        const int j0 = lane * 4;
        for (int p = 0; p < 2; ++p) {
            const int n0 = (warp + p * 16) * 4;
            const float* a0 = sA + min(n0 + 0, 99) * 132;
            const float* a1 = sA + min(n0 + 1, 99) * 132;
            const float* a2 = sA + min(n0 + 2, 99) * 132;
            const float* a3 = sA + min(n0 + 3, 99) * 132;
            float ak[4][4] = {{0.f}}, av[4][4] = {{0.f}};
            #pragma unroll 4
            for (int e = 0; e < EE; ++e) {
                const float4 wk = *reinterpret_cast<const float4*>(Wk + e * 128 + j0);
                const float4 wv = *reinterpret_cast<const float4*>(Wv + e * 128 + j0);
                const float a[4] = {a0[e], a1[e], a2[e], a3[e]};
                #pragma unroll
                for (int i = 0; i < 4; ++i) {
                    ak[i][0] += a[i] * wk.x; ak[i][1] += a[i] * wk.y;
                    ak[i][2] += a[i] * wk.z; ak[i][3] += a[i] * wk.w;
                    av[i][0] += a[i] * wv.x; av[i][1] += a[i] * wv.y;
                    av[i][2] += a[i] * wv.z; av[i][3] += a[i] * wv.w;
                }
            }
            #pragma unroll
            for (int i = 0; i < 4; ++i) {
                if (n0 + i < NN) {
                    *reinterpret_cast<float4*>(sK + (n0 + i) * 132 + j0) =
                        make_float4(ak[i][0], ak[i][1], ak[i][2], ak[i][3]);
                    *reinterpret_cast<float4*>(sV + (n0 + i) * 132 + j0) =
                        make_float4(av[i][0], av[i][1], av[i][2], av[i][3]);
                }
            }
        }
    }
    __syncthreads();

    // ---------------- Phase C: load last -> sA; q = qg + last@(Wqf+Wql) -> sQ --
    for (int idx = tid; idx < GG * 32; idx += NT) {
        int g  = idx >> 5;
        int e4 = (idx & 31) * 4;
        float4 v = *reinterpret_cast<const float4*>(lastB + g * EE + e4);
        *reinterpret_cast<float4*>(sA + g * 132 + e4) = v;
    }
    __syncthreads();

    {
        const int j0 = lane * 4;
        const float4 qg4 = *reinterpret_cast<const float4*>(sQg + j0);
        for (int p = 0; p < 2; ++p) {
            const int g0 = (warp + p * 16) * 4;
            const float* a0 = sA + min(g0 + 0, 99) * 132;
            const float* a1 = sA + min(g0 + 1, 99) * 132;
            const float* a2 = sA + min(g0 + 2, 99) * 132;
            const float* a3 = sA + min(g0 + 3, 99) * 132;
            float acc[4][4] = {{0.f}};
            #pragma unroll 4
            for (int e = 0; e < EE; ++e) {
                const float4 wf = *reinterpret_cast<const float4*>(Wqf + e * 128 + j0);
                const float4 wl = *reinterpret_cast<const float4*>(Wql + e * 128 + j0);
                const float wx = wf.x + wl.x, wy = wf.y + wl.y;
                const float wz = wf.z + wl.z, ww = wf.w + wl.w;
                const float a[4] = {a0[e], a1[e], a2[e], a3[e]};
                #pragma unroll
                for (int i = 0; i < 4; ++i) {
                    acc[i][0] += a[i] * wx; acc[i][1] += a[i] * wy;
                    acc[i][2] += a[i] * wz; acc[i][3] += a[i] * ww;
                }
            }
            #pragma unroll
            for (int i = 0; i < 4; ++i) {
                if (g0 + i < GG) {
                    *reinterpret_cast<float4*>(sQ + (g0 + i) * 132 + j0) =
                        make_float4(acc[i][0] + qg4.x, acc[i][1] + qg4.y,
                                    acc[i][2] + qg4.z, acc[i][3] + qg4.w);
                }
            }
        }
    }
    __syncthreads();

    // ---------------- Phase D: multi-head attention (flash, online softmax) ----
    // attn_out written into sA (last-node data is dead).
    {
        const int g    = tid & 127;
        const int hsel = tid >> 7;          // 0..3
        for (int hb = 0; hb < HH; hb += 4) {
            const int h  = hb + hsel;
            if (g < GG) {
                const int c0 = h * DD;
                float q[DD];
                #pragma unroll
                for (int d = 0; d < DD; ++d) q[d] = sQ[g * 132 + c0 + d];
                float m = -1e30f, l = 0.f, acc[DD];
                #pragma unroll
                for (int d = 0; d < DD; ++d) acc[d] = 0.f;
                const float* mrow = maskB + g * NN;
                for (int n = 0; n < NN; ++n) {
                    const float* kr = sK + n * 132 + c0;
                    float s = 0.f;
                    #pragma unroll
                    for (int d = 0; d < DD; ++d) s += q[d] * kr[d];
                    s = s * 0.25f + mrow[n];           // 1/sqrt(16) + mask
                    const float mn = fmaxf(m, s);
                    const float c  = __expf(m - mn);
                    const float pp = __expf(s - mn);
                    l = l * c + pp;
                    const float* vr = sV + n * 132 + c0;
                    #pragma unroll
                    for (int d = 0; d < DD; ++d) acc[d] = acc[d] * c + pp * vr[d];
                    m = mn;
                }
                const float rl = __fdividef(1.f, l);
                #pragma unroll
                for (int d = 0; d < DD; ++d) sA[g * 132 + c0 + d] = acc[d] * rl;
            }
        }
    }
    __syncthreads();

    // ---------------- Phase E: mh = attn_out @ Wc + bc -> sQ -------------------
    {
        const int j0 = lane * 4;
        const float4 b4 = *reinterpret_cast<const float4*>(bc + j0);
        for (int p = 0; p < 2; ++p) {
            const int g0 = (warp + p * 16) * 4;
            const float* a0 = sA + min(g0 + 0, 99) * 132;
            const float* a1 = sA + min(g0 + 1, 99) * 132;
            const float* a2 = sA + min(g0 + 2, 99) * 132;
            const float* a3 = sA + min(g0 + 3, 99) * 132;
            float acc[4][4] = {{0.f}};
            #pragma unroll 4
            for (int e = 0; e < EE; ++e) {
                const float4 w = *reinterpret_cast<const float4*>(Wc + e * 128 + j0);
                const float a[4] = {a0[e], a1[e], a2[e], a3[e]};
                #pragma unroll
                for (int i = 0; i < 4; ++i) {
                    acc[i][0] += a[i] * w.x; acc[i][1] += a[i] * w.y;
                    acc[i][2] += a[i] * w.z; acc[i][3] += a[i] * w.w;
                }
            }
            #pragma unroll
            for (int i = 0; i < 4; ++i) {
                if (g0 + i < GG) {
                    *reinterpret_cast<float4*>(sQ + (g0 + i) * 132 + j0) =
                        make_float4(acc[i][0] + b4.x, acc[i][1] + b4.y,
                                    acc[i][2] + b4.z, acc[i][3] + b4.w);
                }
            }
        }
    }
    __syncthreads();

    // ---------------- Phase F0: reload enc transposed -> sK as encT[e][n] ------
    for (int idx = tid; idx < NN * 32; idx += NT) {
        int n  = idx >> 5;
        int e4 = (idx & 31) * 4;
        float4 v = *reinterpret_cast<const float4*>(encB + n * EE + e4);
        sK[(e4 + 0) * 100 + n] = v.x;
        sK[(e4 + 1) * 100 + n] = v.y;
        sK[(e4 + 2) * 100 + n] = v.z;
        sK[(e4 + 3) * 100 + n] = v.w;
    }
    __syncthreads();

    // ---------------- Phase F1: pointer scores, tanh clip -> S in sV -----------
    {
        const int n0 = lane * 4;
        const float rsE = 0.08838834764831845f;   // 1/sqrt(128)
        for (int p = 0; p < 2; ++p) {
            const int g0 = (warp + p * 16) * 4;
            const float* a0 = sQ + min(g0 + 0, 99) * 132;
            const float* a1 = sQ + min(g0 + 1, 99) * 132;
            const float* a2 = sQ + min(g0 + 2, 99) * 132;
            const float* a3 = sQ + min(g0 + 3, 99) * 132;
            float acc[4][4] = {{0.f}};
            #pragma unroll 4
            for (int e = 0; e < EE; ++e) {
                const float4 bn = *reinterpret_cast<const float4*>(sK + e * 100 + n0);
                const float a[4] = {a0[e], a1[e], a2[e], a3[e]};
                #pragma unroll
                for (int i = 0; i < 4; ++i) {
                    acc[i][0] += a[i] * bn.x; acc[i][1] += a[i] * bn.y;
                    acc[i][2] += a[i] * bn.z; acc[i][3] += a[i] * bn.w;
                }
            }
            if (lane < 25) {                       // n0..n0+3 all < 100
                #pragma unroll
                for (int i = 0; i < 4; ++i) {
                    if (g0 + i < GG) {
                        float4 o;
                        o.x = 10.f * tanh_acc(acc[i][0] * rsE);
                        o.y = 10.f * tanh_acc(acc[i][1] * rsE);
                        o.z = 10.f * tanh_acc(acc[i][2] * rsE);
                        o.w = 10.f * tanh_acc(acc[i][3] * rsE);
                        *reinterpret_cast<float4*>(sV + (g0 + i) * 104 + n0) = o;
                    }
                }
            }
        }
    }
    __syncthreads();

    // ---------------- Phase F2: masked softmax per row, write probs ------------
    for (int g = warp; g < GG; g += 16) {
        float v[4];
        float mx = -1e30f;
        #pragma unroll
        for (int r = 0; r < 4; ++r) {
            const int n = lane + r * 32;
            float x = -1e30f;
            if (n < NN) x = sV[g * 104 + n] + maskB[g * NN + n];
            v[r] = x;
            mx = fmaxf(mx, x);
        }
        #pragma unroll
        for (int o = 16; o > 0; o >>= 1) mx = fmaxf(mx, __shfl_xor_sync(0xffffffffu, mx, o));
        float sum = 0.f;
        #pragma unroll
        for (int r = 0; r < 4; ++r) {
            const int n = lane + r * 32;
            float e = (n < NN) ? __expf(v[r] - mx) : 0.f;
            v[r] = e;
            sum += e;
        }
        #pragma unroll
        for (int o = 16; o > 0; o >>= 1) sum += __shfl_xor_sync(0xffffffffu, sum, o);
        const float inv = __fdividef(1.f, sum);
        #pragma unroll
        for (int r = 0; r < 4; ++r) {
            const int n = lane + r * 32;
            if (n < NN) outB[g * NN + n] = v[r] * inv;
        }
    }
}

extern "C" void kernel_launch(void* const* d_in, const int* in_sizes, int n_in,
                              void* d_out, int out_size) {
    const float* enc  = (const float*)d_in[0];
    const float* last = (const float*)d_in[1];
    const float* mask = (const float*)d_in[2];
    const float* Wqg  = (const float*)d_in[3];
    const float* Wqf  = (const float*)d_in[4];
    const float* Wql  = (const float*)d_in[5];
    const float* Wk   = (const float*)d_in[6];
    const float* Wv   = (const float*)d_in[7];
    const float* Wc   = (const float*)d_in[8];
    const float* bc   = (const float*)d_in[9];
    float* out = (float*)d_out;

    const size_t smem_bytes = (size_t)SMEM_FLOATS * sizeof(float);
    cudaFuncSetAttribute(pomo_decoder_kernel,
                         cudaFuncAttributeMaxDynamicSharedMemorySize,
                         (int)smem_bytes);
    pomo_decoder_kernel<<<BB, NT, smem_bytes>>>(enc, last, mask, Wqg, Wqf, Wql,
                                                Wk, Wv, Wc, bc, out);
}

// round 2
// speedup vs baseline: 1.0033x; 1.0033x over previous
#include <cuda_runtime.h>
#include <math.h>

// Problem constants
#define BB 2048
#define NN 100      // nodes
#define GG 100      // group
#define EE 128      // embedding
#define HH 8        // heads
#define DD 16       // key dim
#define NT 512      // threads per CTA

// Shared memory layout (floats). Row stride 132 (16B-aligned, odd/32 bank skew).
#define SA_OFF   0        // [100][132] enc -> last -> attn_out
#define SK_OFF   13200    // [100][132] k   -> encT [128][100]
#define SV_OFF   26400    // [100][132] v   -> S scores [100][104]
#define SQ_OFF   39600    // [100][132] q   -> mh
#define SG_OFF   52800    // [128] graph mean
#define SQG_OFF  52928    // [128] q_graph
#define SMEM_FLOATS 53056

__device__ __forceinline__ float tanh_acc(float x) {
    // tanh via exp, ~1e-6 rel error (far better than tanh.approx)
    float ax = fabsf(x);
    float e = __expf(-2.0f * ax);
    float t = __fdividef(1.0f - e, 1.0f + e);
    return copysignf(t, x);
}

__global__ __launch_bounds__(NT, 1)
void pomo_decoder_kernel(const float* __restrict__ enc,   // [B,N,E]
                         const float* __restrict__ last,  // [B,G,E]
                         const float* __restrict__ mask,  // [B,G,N]
                         const float* __restrict__ Wqg,   // [E,128]
                         const float* __restrict__ Wqf,   // [E,128]
                         const float* __restrict__ Wql,   // [E,128]
                         const float* __restrict__ Wk,    // [E,128]
                         const float* __restrict__ Wv,    // [E,128]
                         const float* __restrict__ Wc,    // [128,E]
                         const float* __restrict__ bc,    // [E]
                         float* __restrict__ out)         // [B,G,N]
{
    extern __shared__ float sm[];
    float* sA  = sm + SA_OFF;
    float* sK  = sm + SK_OFF;
    float* sV  = sm + SV_OFF;
    float* sQ  = sm + SQ_OFF;
    float* sG  = sm + SG_OFF;
    float* sQg = sm + SQG_OFF;

    const int b    = blockIdx.x;
    const int tid  = threadIdx.x;
    const int lane = tid & 31;
    const int warp = tid >> 5;   // 0..15

    const float* encB  = enc  + (size_t)b * NN * EE;
    const float* lastB = last + (size_t)b * GG * EE;
    const float* maskB = mask + (size_t)b * GG * NN;
    float*       outB  = out  + (size_t)b * GG * NN;

    // ---------------- Phase A: load enc -> sA, graph mean, q_graph -------------
    for (int idx = tid; idx < NN * 32; idx += NT) {
        int n  = idx >> 5;
        int e4 = (idx & 31) * 4;
        float4 v = *reinterpret_cast<const float4*>(encB + n * EE + e4);
        *reinterpret_cast<float4*>(sA + n * 132 + e4) = v;
    }
    __syncthreads();

    if (tid < EE) {
        float s = 0.f;
        #pragma unroll 4
        for (int n = 0; n < NN; ++n) s += sA[n * 132 + tid];
        sG[tid] = s * (1.0f / NN);
    }
    __syncthreads();

    if (tid < EE) {
        float s = 0.f;
        #pragma unroll 4
        for (int e = 0; e < EE; ++e) s += sG[e] * Wqg[e * 128 + tid];
        sQg[tid] = s;
    }
    // (no sync needed before B: B doesn't touch sQg; sync before C covers it)

    // ---------------- Phase B: k = enc@Wk, v = enc@Wv -> sK, sV ----------------
    {
        const int j0 = lane * 4;
        for (int p = 0; p < 2; ++p) {
            const int n0 = (warp + p * 16) * 4;
            const float* a0 = sA + min(n0 + 0, 99) * 132;
            const float* a1 = sA + min(n0 + 1, 99) * 132;
            const float* a2 = sA + min(n0 + 2, 99) * 132;
            const float* a3 = sA + min(n0 + 3, 99) * 132;
            float ak[4][4] = {{0.f}}, av[4][4] = {{0.f}};
            #pragma unroll 4
            for (int e = 0; e < EE; ++e) {
                const float4 wk = *reinterpret_cast<const float4*>(Wk + e * 128 + j0);
                const float4 wv = *reinterpret_cast<const float4*>(Wv + e * 128 + j0);
                const float a[4] = {a0[e], a1[e], a2[e], a3[e]};
                #pragma unroll
                for (int i = 0; i < 4; ++i) {
                    ak[i][0] += a[i] * wk.x; ak[i][1] += a[i] * wk.y;
                    ak[i][2] += a[i] * wk.z; ak[i][3] += a[i] * wk.w;
                    av[i][0] += a[i] * wv.x; av[i][1] += a[i] * wv.y;
                    av[i][2] += a[i] * wv.z; av[i][3] += a[i] * wv.w;
                }
            }
            #pragma unroll
            for (int i = 0; i < 4; ++i) {
                if (n0 + i < NN) {
                    *reinterpret_cast<float4*>(sK + (n0 + i) * 132 + j0) =
                        make_float4(ak[i][0], ak[i][1], ak[i][2], ak[i][3]);
                    *reinterpret_cast<float4*>(sV + (n0 + i) * 132 + j0) =
                        make_float4(av[i][0], av[i][1], av[i][2], av[i][3]);
                }
            }
        }
    }
    __syncthreads();

    // ---------------- Phase C: load last -> sA; q = qg + last@(Wqf+Wql) -> sQ --
    for (int idx = tid; idx < GG * 32; idx += NT) {
        int g  = idx >> 5;
        int e4 = (idx & 31) * 4;
        float4 v = *reinterpret_cast<const float4*>(lastB + g * EE + e4);
        *reinterpret_cast<float4*>(sA + g * 132 + e4) = v;
    }
    __syncthreads();

    {
        const int j0 = lane * 4;
        const float4 qg4 = *reinterpret_cast<const float4*>(sQg + j0);
        for (int p = 0; p < 2; ++p) {
            const int g0 = (warp + p * 16) * 4;
            const float* a0 = sA + min(g0 + 0, 99) * 132;
            const float* a1 = sA + min(g0 + 1, 99) * 132;
            const float* a2 = sA + min(g0 + 2, 99) * 132;
            const float* a3 = sA + min(g0 + 3, 99) * 132;
            float acc[4][4] = {{0.f}};
            #pragma unroll 4
            for (int e = 0; e < EE; ++e) {
                const float4 wf = *reinterpret_cast<const float4*>(Wqf + e * 128 + j0);
                const float4 wl = *reinterpret_cast<const float4*>(Wql + e * 128 + j0);
                const float wx = wf.x + wl.x, wy = wf.y + wl.y;
                const float wz = wf.z + wl.z, ww = wf.w + wl.w;
                const float a[4] = {a0[e], a1[e], a2[e], a3[e]};
                #pragma unroll
                for (int i = 0; i < 4; ++i) {
                    acc[i][0] += a[i] * wx; acc[i][1] += a[i] * wy;
                    acc[i][2] += a[i] * wz; acc[i][3] += a[i] * ww;
                }
            }
            #pragma unroll
            for (int i = 0; i < 4; ++i) {
                if (g0 + i < GG) {
                    *reinterpret_cast<float4*>(sQ + (g0 + i) * 132 + j0) =
                        make_float4(acc[i][0] + qg4.x, acc[i][1] + qg4.y,
                                    acc[i][2] + qg4.z, acc[i][3] + qg4.w);
                }
            }
        }
    }
    __syncthreads();

    // ---------------- Phase D: multi-head attention (flash, online softmax) ----
    // attn_out written into sA (last-node data is dead).
    {
        const int g    = tid & 127;
        const int hsel = tid >> 7;          // 0..3
        for (int hb = 0; hb < HH; hb += 4) {
            const int h  = hb + hsel;
            if (g < GG) {
                const int c0 = h * DD;
                float q[DD];
                #pragma unroll
                for (int d = 0; d < DD; ++d) q[d] = sQ[g * 132 + c0 + d];
                float m = -1e30f, l = 0.f, acc[DD];
                #pragma unroll
                for (int d = 0; d < DD; ++d) acc[d] = 0.f;
                const float* mrow = maskB + g * NN;
                for (int n = 0; n < NN; ++n) {
                    const float* kr = sK + n * 132 + c0;
                    float s = 0.f;
                    #pragma unroll
                    for (int d = 0; d < DD; ++d) s += q[d] * kr[d];
                    s = s * 0.25f + mrow[n];           // 1/sqrt(16) + mask
                    const float mn = fmaxf(m, s);
                    const float c  = __expf(m - mn);
                    const float pp = __expf(s - mn);
                    l = l * c + pp;
                    const float* vr = sV + n * 132 + c0;
                    #pragma unroll
                    for (int d = 0; d < DD; ++d) acc[d] = acc[d] * c + pp * vr[d];
                    m = mn;
                }
                const float rl = __fdividef(1.f, l);
                #pragma unroll
                for (int d = 0; d < DD; ++d) sA[g * 132 + c0 + d] = acc[d] * rl;
            }
        }
    }
    __syncthreads();

    // ---------------- Phase E: mh = attn_out @ Wc + bc -> sQ -------------------
    {
        const int j0 = lane * 4;
        const float4 b4 = *reinterpret_cast<const float4*>(bc + j0);
        for (int p = 0; p < 2; ++p) {
            const int g0 = (warp + p * 16) * 4;
            const float* a0 = sA + min(g0 + 0, 99) * 132;
            const float* a1 = sA + min(g0 + 1, 99) * 132;
            const float* a2 = sA + min(g0 + 2, 99) * 132;
            const float* a3 = sA + min(g0 + 3, 99) * 132;
            float acc[4][4] = {{0.f}};
            #pragma unroll 4
            for (int e = 0; e < EE; ++e) {
                const float4 w = *reinterpret_cast<const float4*>(Wc + e * 128 + j0);
                const float a[4] = {a0[e], a1[e], a2[e], a3[e]};
                #pragma unroll
                for (int i = 0; i < 4; ++i) {
                    acc[i][0] += a[i] * w.x; acc[i][1] += a[i] * w.y;
                    acc[i][2] += a[i] * w.z; acc[i][3] += a[i] * w.w;
                }
            }
            #pragma unroll
            for (int i = 0; i < 4; ++i) {
                if (g0 + i < GG) {
                    *reinterpret_cast<float4*>(sQ + (g0 + i) * 132 + j0) =
                        make_float4(acc[i][0] + b4.x, acc[i][1] + b4.y,
                                    acc[i][2] + b4.z, acc[i][3] + b4.w);
                }
            }
        }
    }
    __syncthreads();

    // ---------------- Phase F0: reload enc transposed -> sK as encT[e][n] ------
    for (int idx = tid; idx < NN * 32; idx += NT) {
        int n  = idx >> 5;
        int e4 = (idx & 31) * 4;
        float4 v = *reinterpret_cast<const float4*>(encB + n * EE + e4);
        sK[(e4 + 0) * 100 + n] = v.x;
        sK[(e4 + 1) * 100 + n] = v.y;
        sK[(e4 + 2) * 100 + n] = v.z;
        sK[(e4 + 3) * 100 + n] = v.w;
    }
    __syncthreads();

    // ---------------- Phase F1: pointer scores, tanh clip -> S in sV -----------
    {
        const int n0 = lane * 4;
        const float rsE = 0.08838834764831845f;   // 1/sqrt(128)
        for (int p = 0; p < 2; ++p) {
            const int g0 = (warp + p * 16) * 4;
            const float* a0 = sQ + min(g0 + 0, 99) * 132;
            const float* a1 = sQ + min(g0 + 1, 99) * 132;
            const float* a2 = sQ + min(g0 + 2, 99) * 132;
            const float* a3 = sQ + min(g0 + 3, 99) * 132;
            float acc[4][4] = {{0.f}};
            #pragma unroll 4
            for (int e = 0; e < EE; ++e) {
                const float4 bn = *reinterpret_cast<const float4*>(sK + e * 100 + n0);
                const float a[4] = {a0[e], a1[e], a2[e], a3[e]};
                #pragma unroll
                for (int i = 0; i < 4; ++i) {
                    acc[i][0] += a[i] * bn.x; acc[i][1] += a[i] * bn.y;
                    acc[i][2] += a[i] * bn.z; acc[i][3] += a[i] * bn.w;
                }
            }
            if (lane < 25) {                       // n0..n0+3 all < 100
                #pragma unroll
                for (int i = 0; i < 4; ++i) {
                    if (g0 + i < GG) {
                        float4 o;
                        o.x = 10.f * tanh_acc(acc[i][0] * rsE);
                        o.y = 10.f * tanh_acc(acc[i][1] * rsE);
                        o.z = 10.f * tanh_acc(acc[i][2] * rsE);
                        o.w = 10.f * tanh_acc(acc[i][3] * rsE);
                        *reinterpret_cast<float4*>(sV + (g0 + i) * 104 + n0) = o;
                    }
                }
            }
        }
    }
    __syncthreads();

    // ---------------- Phase F2: masked softmax per row, write probs ------------
    for (int g = warp; g < GG; g += 16) {
        float v[4];
        float mx = -1e30f;
        #pragma unroll
        for (int r = 0; r < 4; ++r) {
            const int n = lane + r * 32;
            float x = -1e30f;
            if (n < NN) x = sV[g * 104 + n] + maskB[g * NN + n];
            v[r] = x;
            mx = fmaxf(mx, x);
        }
        #pragma unroll
        for (int o = 16; o > 0; o >>= 1) mx = fmaxf(mx, __shfl_xor_sync(0xffffffffu, mx, o));
        float sum = 0.f;
        #pragma unroll
        for (int r = 0; r < 4; ++r) {
            const int n = lane + r * 32;
            float e = (n < NN) ? __expf(v[r] - mx) : 0.f;
            v[r] = e;
            sum += e;
        }
        #pragma unroll
        for (int o = 16; o > 0; o >>= 1) sum += __shfl_xor_sync(0xffffffffu, sum, o);
        const float inv = __fdividef(1.f, sum);
        #pragma unroll
        for (int r = 0; r < 4; ++r) {
            const int n = lane + r * 32;
            if (n < NN) outB[g * NN + n] = v[r] * inv;
        }
    }
}

extern "C" void kernel_launch(void* const* d_in, const int* in_sizes, int n_in,
                              void* d_out, int out_size) {
    const float* enc  = (const float*)d_in[0];
    const float* last = (const float*)d_in[1];
    const float* mask = (const float*)d_in[2];
    const float* Wqg  = (const float*)d_in[3];
    const float* Wqf  = (const float*)d_in[4];
    const float* Wql  = (const float*)d_in[5];
    const float* Wk   = (const float*)d_in[6];
    const float* Wv   = (const float*)d_in[7];
    const float* Wc   = (const float*)d_in[8];
    const float* bc   = (const float*)d_in[9];
    float* out = (float*)d_out;

    const size_t smem_bytes = (size_t)SMEM_FLOATS * sizeof(float);
    cudaFuncSetAttribute(pomo_decoder_kernel,
                         cudaFuncAttributeMaxDynamicSharedMemorySize,
                         (int)smem_bytes);
    pomo_decoder_kernel<<<BB, NT, smem_bytes>>>(enc, last, mask, Wqg, Wqf, Wql,
                                                Wk, Wv, Wc, bc, out);
}

// round 3
// speedup vs baseline: 1.0657x; 1.0622x over previous
#include <cuda_runtime.h>
#include <math.h>

#define BB 2048
#define NN 100
#define GG 100
#define EE 128
#define NT 1024

// smem regions (floats)
#define SA_OFF   0        // enc -> last -> mask(flat 10000)
#define SK_OFF   13200    // k -> mh
#define SV_OFF   26400    // mean scratch -> v -> encT[128][100]
#define SQ_OFF   39600    // q -> attn -> S[100][104]
#define SG_OFF   52800    // graph mean [128]
#define SQG_OFF  52928    // q_graph [128]
#define SMEM_FLOATS 53056

typedef unsigned long long ull;

__device__ __forceinline__ ull bcast2(float a) {
    ull r; asm("mov.b64 %0, {%1,%1};" : "=l"(r) : "f"(a)); return r;
}
__device__ __forceinline__ ull ffma2(ull a, ull b, ull c) {
    ull d; asm("fma.rn.f32x2 %0, %1, %2, %3;" : "=l"(d) : "l"(a), "l"(b), "l"(c));
    return d;
}
__device__ __forceinline__ float4 unpack4(ull a, ull b) {
    float4 r;
    asm("mov.b64 {%0,%1}, %2;" : "=f"(r.x), "=f"(r.y) : "l"(a));
    asm("mov.b64 {%0,%1}, %2;" : "=f"(r.z), "=f"(r.w) : "l"(b));
    return r;
}
__device__ __forceinline__ float tanh_acc(float x) {
    float ax = fabsf(x);
    float e = __expf(-2.0f * ax);
    float t = __fdividef(1.0f - e, 1.0f + e);
    return copysignf(t, x);
}

__device__ float g_Wfl[EE * 128];

__global__ void prep_kernel(const float* __restrict__ Wqf,
                            const float* __restrict__ Wql) {
    int i = blockIdx.x * blockDim.x + threadIdx.x;
    if (i < EE * 128) g_Wfl[i] = Wqf[i] + Wql[i];
}

// 8-row x 4-col tile: A rows from smem (stride lda), W [128][128] row-major global.
__device__ __forceinline__ void gemm8(const float* sBase, int r0, int lda,
                                      const float* __restrict__ W, int j0,
                                      ull acc[8][2]) {
    int off[8];
    #pragma unroll
    for (int i = 0; i < 8; ++i) off[i] = min(r0 + i, NN - 1) * lda;
    #pragma unroll
    for (int i = 0; i < 8; ++i) { acc[i][0] = 0ULL; acc[i][1] = 0ULL; }
    #pragma unroll 4
    for (int e = 0; e < EE; ++e) {
        const ulonglong2 w2 = *reinterpret_cast<const ulonglong2*>(W + e * 128 + j0);
        #pragma unroll
        for (int i = 0; i < 8; ++i) {
            ull ap = bcast2(sBase[off[i] + e]);
            acc[i][0] = ffma2(ap, w2.x, acc[i][0]);
            acc[i][1] = ffma2(ap, w2.y, acc[i][1]);
        }
    }
}

__global__ __launch_bounds__(NT, 1)
void pomo_decoder_kernel(const float* __restrict__ enc,
                         const float* __restrict__ last,
                         const float* __restrict__ mask,
                         const float* __restrict__ Wqg,
                         const float* __restrict__ Wk,
                         const float* __restrict__ Wv,
                         const float* __restrict__ Wc,
                         const float* __restrict__ bc,
                         float* __restrict__ out) {
    extern __shared__ float sm[];
    float* sA  = sm + SA_OFF;
    float* sK  = sm + SK_OFF;
    float* sV  = sm + SV_OFF;
    float* sQ  = sm + SQ_OFF;
    float* sG  = sm + SG_OFF;
    float* sQg = sm + SQG_OFF;

    const int b    = blockIdx.x;
    const int tid  = threadIdx.x;
    const int lane = tid & 31;
    const int warp = tid >> 5;   // 0..31
    const int j0   = lane * 4;

    const float* encB  = enc  + (size_t)b * NN * EE;
    const float* lastB = last + (size_t)b * GG * EE;
    const float* maskB = mask + (size_t)b * GG * NN;
    float*       outB  = out  + (size_t)b * GG * NN;

    // A: enc -> sA
    for (int idx = tid; idx < NN * 32; idx += NT) {
        int n = idx >> 5, e4 = (idx & 31) * 4;
        *reinterpret_cast<float4*>(sA + n * 132 + e4) =
            *reinterpret_cast<const float4*>(encB + n * EE + e4);
    }
    __syncthreads();

    // graph mean: 8 partials per e into sV scratch
    {
        int part = tid >> 7, e = tid & 127;
        int rb = part * 13, re = min(rb + 13, NN);
        float s = 0.f;
        for (int n = rb; n < re; ++n) s += sA[n * 132 + e];
        sV[part * 128 + e] = s;
    }
    __syncthreads();
    if (tid < EE) {
        float s = 0.f;
        #pragma unroll
        for (int p = 0; p < 8; ++p) s += sV[p * 128 + tid];
        sG[tid] = s * (1.0f / NN);
    }
    __syncthreads();

    // B: k (warps 0-12), v (warps 13-25), q_graph (warps 26-29)
    if (warp < 13) {
        ull acc[8][2];
        const int r0 = warp * 8;
        gemm8(sA, r0, 132, Wk, j0, acc);
        #pragma unroll
        for (int i = 0; i < 8; ++i)
            if (r0 + i < NN)
                *reinterpret_cast<float4*>(sK + (r0 + i) * 132 + j0) =
                    unpack4(acc[i][0], acc[i][1]);
    } else if (warp < 26) {
        ull acc[8][2];
        const int r0 = (warp - 13) * 8;
        gemm8(sA, r0, 132, Wv, j0, acc);
        #pragma unroll
        for (int i = 0; i < 8; ++i)
            if (r0 + i < NN)
                *reinterpret_cast<float4*>(sV + (r0 + i) * 132 + j0) =
                    unpack4(acc[i][0], acc[i][1]);
    } else if (warp < 30) {
        int j = (warp - 26) * 32 + lane;
        float s = 0.f;
        #pragma unroll 4
        for (int e = 0; e < EE; ++e) s += sG[e] * Wqg[e * 128 + j];
        sQg[j] = s;
    }
    __syncthreads();

    // C: last -> sA
    for (int idx = tid; idx < GG * 32; idx += NT) {
        int g = idx >> 5, e4 = (idx & 31) * 4;
        *reinterpret_cast<float4*>(sA + g * 132 + e4) =
            *reinterpret_cast<const float4*>(lastB + g * EE + e4);
    }
    __syncthreads();

    // q = qg + last @ (Wqf+Wql)  (warps 0-12)
    if (warp < 13) {
        ull acc[8][2];
        const int r0 = warp * 8;
        gemm8(sA, r0, 132, g_Wfl, j0, acc);
        const float4 qg4 = *reinterpret_cast<const float4*>(sQg + j0);
        #pragma unroll
        for (int i = 0; i < 8; ++i)
            if (r0 + i < GG) {
                float4 r = unpack4(acc[i][0], acc[i][1]);
                r.x += qg4.x; r.y += qg4.y; r.z += qg4.z; r.w += qg4.w;
                *reinterpret_cast<float4*>(sQ + (r0 + i) * 132 + j0) = r;
            }
    }
    __syncthreads();

    // stage mask -> sA (flat [g*100+n])
    for (int idx = tid; idx < (GG * NN) / 4; idx += NT)
        reinterpret_cast<float4*>(sA)[idx] =
            reinterpret_cast<const float4*>(maskB)[idx];
    __syncthreads();

    // D: attention, one (g,h) per thread; attn overwrites q in sQ
    {
        const int g = tid & 127;
        const int h = tid >> 7;     // 0..7
        if (g < GG) {
            const int c0 = h * 16;
            float q[16], acc[16];
            #pragma unroll
            for (int d = 0; d < 16; ++d) { q[d] = sQ[g * 132 + c0 + d]; acc[d] = 0.f; }
            float m = -1e30f, l = 0.f;
            const float* mrow = sA + g * NN;
            for (int n = 0; n < NN; ++n) {
                const float* kr = sK + n * 132 + c0;
                float s = 0.f;
                #pragma unroll
                for (int d = 0; d < 16; ++d) s += q[d] * kr[d];
                s = s * 0.25f + mrow[n];
                const float mn = fmaxf(m, s);
                const float c  = __expf(m - mn);
                const float p  = __expf(s - mn);
                l = l * c + p;
                const float* vr = sV + n * 132 + c0;
                #pragma unroll
                for (int d = 0; d < 16; ++d) acc[d] = acc[d] * c + p * vr[d];
                m = mn;
            }
            const float rl = __fdividef(1.f, l);
            #pragma unroll
            for (int d = 0; d < 16; ++d) sQ[g * 132 + c0 + d] = acc[d] * rl;
        }
    }
    __syncthreads();

    // E: mh = attn @ Wc + bc -> sK (warps 0-12) || encT -> sV (warps 13-31)
    if (warp < 13) {
        ull acc[8][2];
        const int r0 = warp * 8;
        gemm8(sQ, r0, 132, Wc, j0, acc);
        const float4 b4 = *reinterpret_cast<const float4*>(bc + j0);
        #pragma unroll
        for (int i = 0; i < 8; ++i)
            if (r0 + i < GG) {
                float4 r = unpack4(acc[i][0], acc[i][1]);
                r.x += b4.x; r.y += b4.y; r.z += b4.z; r.w += b4.w;
                *reinterpret_cast<float4*>(sK + (r0 + i) * 132 + j0) = r;
            }
    } else {
        for (int idx = tid - 13 * 32; idx < NN * 32; idx += NT - 13 * 32) {
            int n = idx >> 5, e4 = (idx & 31) * 4;
            float4 v = *reinterpret_cast<const float4*>(encB + n * EE + e4);
            sV[(e4 + 0) * 100 + n] = v.x;
            sV[(e4 + 1) * 100 + n] = v.y;
            sV[(e4 + 2) * 100 + n] = v.z;
            sV[(e4 + 3) * 100 + n] = v.w;
        }
    }
    __syncthreads();

    // F1: S = 10*tanh((mh @ encT)/sqrt(128)) -> sQ stride 104 (warps 0-12)
    if (warp < 13 && lane < 25) {
        const int n0 = j0;          // lane*4, < 100
        const int r0 = warp * 8;
        int off[8];
        #pragma unroll
        for (int i = 0; i < 8; ++i) off[i] = min(r0 + i, NN - 1) * 132;
        ull acc[8][2];
        #pragma unroll
        for (int i = 0; i < 8; ++i) { acc[i][0] = 0ULL; acc[i][1] = 0ULL; }
        #pragma unroll 4
        for (int e = 0; e < EE; ++e) {
            const ulonglong2 b2 = *reinterpret_cast<const ulonglong2*>(sV + e * 100 + n0);
            #pragma unroll
            for (int i = 0; i < 8; ++i) {
                ull ap = bcast2(sK[off[i] + e]);
                acc[i][0] = ffma2(ap, b2.x, acc[i][0]);
                acc[i][1] = ffma2(ap, b2.y, acc[i][1]);
            }
        }
        const float rsE = 0.08838834764831845f;
        #pragma unroll
        for (int i = 0; i < 8; ++i)
            if (r0 + i < GG) {
                float4 r = unpack4(acc[i][0], acc[i][1]);
                r.x = 10.f * tanh_acc(r.x * rsE);
                r.y = 10.f * tanh_acc(r.y * rsE);
                r.z = 10.f * tanh_acc(r.z * rsE);
                r.w = 10.f * tanh_acc(r.w * rsE);
                *reinterpret_cast<float4*>(sQ + (r0 + i) * 104 + n0) = r;
            }
    }
    __syncthreads();

    // F2: masked softmax per row -> out  (mask from sA)
    for (int g = warp; g < GG; g += 32) {
        float v[4];
        float mx = -1e30f;
        #pragma unroll
        for (int r = 0; r < 4; ++r) {
            const int n = lane + r * 32;
            float x = -1e30f;
            if (n < NN) x = sQ[g * 104 + n] + sA[g * NN + n];
            v[r] = x;
            mx = fmaxf(mx, x);
        }
        #pragma unroll
        for (int o = 16; o > 0; o >>= 1) mx = fmaxf(mx, __shfl_xor_sync(~0u, mx, o));
        float sum = 0.f;
        #pragma unroll
        for (int r = 0; r < 4; ++r) {
            const int n = lane + r * 32;
            float e = (n < NN) ? __expf(v[r] - mx) : 0.f;
            v[r] = e;
            sum += e;
        }
        #pragma unroll
        for (int o = 16; o > 0; o >>= 1) sum += __shfl_xor_sync(~0u, sum, o);
        const float inv = __fdividef(1.f, sum);
        #pragma unroll
        for (int r = 0; r < 4; ++r) {
            const int n = lane + r * 32;
            if (n < NN) outB[g * NN + n] = v[r] * inv;
        }
    }
}

extern "C" void kernel_launch(void* const* d_in, const int* in_sizes, int n_in,
                              void* d_out, int out_size) {
    const float* enc  = (const float*)d_in[0];
    const float* last = (const float*)d_in[1];
    const float* mask = (const float*)d_in[2];
    const float* Wqg  = (const float*)d_in[3];
    const float* Wqf  = (const float*)d_in[4];
    const float* Wql  = (const float*)d_in[5];
    const float* Wk   = (const float*)d_in[6];
    const float* Wv   = (const float*)d_in[7];
    const float* Wc   = (const float*)d_in[8];
    const float* bc   = (const float*)d_in[9];
    float* out = (float*)d_out;

    prep_kernel<<<(EE * 128 + 255) / 256, 256>>>(Wqf, Wql);

    const size_t smem_bytes = (size_t)SMEM_FLOATS * sizeof(float);
    cudaFuncSetAttribute(pomo_decoder_kernel,
                         cudaFuncAttributeMaxDynamicSharedMemorySize,
                         (int)smem_bytes);
    pomo_decoder_kernel<<<BB, NT, smem_bytes>>>(enc, last, mask, Wqg,
                                                Wk, Wv, Wc, bc, out);
}